// round 7
// baseline (speedup 1.0000x reference)
#include <cuda_runtime.h>

// InvDiff: x[64, 4096, 256] fp32
//   d[b,l,f] = x[b,l+1,f] - x[b,l,f]                 (l in [0,4095))
//   y[b,l,f] = x[b,l+1,f] - x[b,0,f]  (l<4094), 0    (l==4094)
// Output = [d flat | y flat]. HBM-ceiling-bound (~6.5 TB/s, traffic at floor).
// This round: block-specialized stream separation. blockIdx.x==0 blocks write
// only the d stream, ==1 blocks write only the y stream. Adjacent bids cover
// the same x rows -> co-scheduled in the same wave -> duplicated reads are
// L2 hits; each block issues one pure sequential write stream.

static constexpr int B   = 64;
static constexpr int L   = 4096;
static constexpr int F   = 256;
static constexpr int F4  = F / 4;         // 64 float4 per row
static constexpr int LD  = L - 1;         // 4095 output rows

__device__ __forceinline__ float4 sub4(float4 a, float4 b) {
    float4 r; r.x = a.x - b.x; r.y = a.y - b.y; r.z = a.z - b.z; r.w = a.w - b.w;
    return r;
}

__global__ __launch_bounds__(512)
void invdiff_kernel(const float4* __restrict__ x, float4* __restrict__ out) {
    const int f  = threadIdx.x;                                   // 0..63
    const int l0 = (blockIdx.y * blockDim.y + threadIdx.y) * 2;   // even row
    const int b  = blockIdx.z;
    if (l0 >= LD) return;

    const int baseIn = b * (L * F4);
    const int outIdx = b * (LD * F4) + l0 * F4 + f;
    const int D      = B * LD * F4;       // float4 count of d block

    const bool has2 = (l0 + 1) < LD;

    // Shared reads (L2-deduped between the paired d/y blocks)
    const float4 xb = x[baseIn + (l0 + 1) * F4 + f];
    float4 xc;
    if (has2) xc = x[baseIn + (l0 + 2) * F4 + f];

    if (blockIdx.x == 0) {
        // ---- d stream only ----
        const float4 xa = x[baseIn + l0 * F4 + f];
        out[outIdx] = sub4(xb, xa);
        if (has2) out[outIdx + F4] = sub4(xc, xb);
    } else {
        // ---- y stream only ----
        const float4 x0 = __ldg(&x[baseIn + f]);   // 1KB/batch, cache-hot

        float4 y0;
        if (l0 < LD - 1) y0 = sub4(xb, x0);
        else { y0.x = 0.f; y0.y = 0.f; y0.z = 0.f; y0.w = 0.f; }
        out[D + outIdx] = y0;

        if (has2) {
            float4 y1;
            if (l0 + 1 < LD - 1) y1 = sub4(xc, x0);
            else { y1.x = 0.f; y1.y = 0.f; y1.z = 0.f; y1.w = 0.f; }
            out[D + outIdx + F4] = y1;
        }
    }
}

extern "C" void kernel_launch(void* const* d_in, const int* in_sizes, int n_in,
                              void* d_out, int out_size) {
    const float4* x = (const float4*)d_in[0];
    float4* out = (float4*)d_out;

    // 2048 l-pairs, 8 pairs per block in y; x-dim selects d vs y stream.
    dim3 block(F4, 8, 1);                            // 512 threads
    dim3 grid(2, (2048 + 7) / 8, B);                 // 2 x 256 x 64 blocks
    invdiff_kernel<<<grid, block>>>(x, out);
}